// round 10
// baseline (speedup 1.0000x reference)
#include <cuda_runtime.h>
#include <math.h>

#define B 64
#define L 2048
#define D 300
#define KW 111
#define V 50000
#define NCHUNK 8         // token chunks per batch row in zacc
#define CTOK 256         // tokens per chunk
#define HL 1024          // conv half-length per block
#define SG2 1140         // halo'd shared length: 1024 + 111 + 4 + pad

// ---- device scratch (no allocs allowed) ----
__device__ float2 vg_scr[V];                 // per-vocab normalized class dots
__device__ float2 opart_scr[B*NCHUNK];       // per-chunk (o0,o1) partials
__device__ float  esum_scr[B*2];             // per-half exp-sum partials

__device__ __forceinline__ void acc3(float4 e, float4 ka, float4 kb,
                                     float& ss, float& d0, float& d1) {
    ss += e.x*e.x + e.y*e.y + e.z*e.z + e.w*e.w;
    d0 += e.x*ka.x + e.y*ka.y + e.z*ka.z + e.w*ka.w;
    d1 += e.x*kb.x + e.y*kb.y + e.z*kb.z + e.w*kb.w;
}

// ---------------------------------------------------------------------------
// Kernel 1: per-VOCAB-row normalized class dots (60MB streaming read).
// FOUR rows per warp, all 12 float4 loads issued before any math; class
// vectors hoisted to registers; combined 12-value butterfly reduction.
// ---------------------------------------------------------------------------
__global__ void __launch_bounds__(256)
vocab_dot_kernel(const float* __restrict__ emb, const float* __restrict__ cls) {
    __shared__ __align__(16) float sc[2*D];
    __shared__ float cninv[2];
    int tid = threadIdx.x, warp = tid >> 5, lane = tid & 31;

    for (int i = tid; i < 2*D; i += 256) sc[i] = cls[i];
    __syncthreads();
    if (warp < 2) {
        float ss = 0.f;
        for (int d = lane; d < D; d += 32) { float v = sc[warp*D + d]; ss += v*v; }
        #pragma unroll
        for (int o = 16; o > 0; o >>= 1) ss += __shfl_xor_sync(0xffffffffu, ss, o);
        if (lane == 0) cninv[warp] = 1.0f / fmaxf(sqrtf(ss), 1e-12f);
    }
    __syncthreads();

    const float4* c0 = (const float4*)sc;
    const float4* c1 = (const float4*)(sc + D);
    bool tail = (lane < 11);
    float4 zf = make_float4(0.f,0.f,0.f,0.f);

    float4 k0 = c0[lane], k1 = c0[lane+32], k2 = tail ? c0[lane+64] : zf;
    float4 m0 = c1[lane], m1 = c1[lane+32], m2 = tail ? c1[lane+64] : zf;

    int rbase = blockIdx.x * 32 + warp * 4;          // 4 rows per warp
    int r0 = min(rbase,     V-1);
    int r1 = min(rbase + 1, V-1);
    int r2 = min(rbase + 2, V-1);
    int r3 = min(rbase + 3, V-1);
    const float4* p0 = (const float4*)(emb + (size_t)r0 * D);
    const float4* p1 = (const float4*)(emb + (size_t)r1 * D);
    const float4* p2 = (const float4*)(emb + (size_t)r2 * D);
    const float4* p3 = (const float4*)(emb + (size_t)r3 * D);

    // issue ALL 12 loads before any math
    float4 A0 = __ldg(p0 + lane), A1 = __ldg(p0 + lane + 32), A2 = tail ? __ldg(p0 + lane + 64) : zf;
    float4 B0 = __ldg(p1 + lane), B1 = __ldg(p1 + lane + 32), B2 = tail ? __ldg(p1 + lane + 64) : zf;
    float4 C0 = __ldg(p2 + lane), C1 = __ldg(p2 + lane + 32), C2 = tail ? __ldg(p2 + lane + 64) : zf;
    float4 D0 = __ldg(p3 + lane), D1 = __ldg(p3 + lane + 32), D2 = tail ? __ldg(p3 + lane + 64) : zf;

    float v[12];
    #pragma unroll
    for (int i = 0; i < 12; i++) v[i] = 0.f;
    acc3(A0, k0, m0, v[0], v[1], v[2]);  acc3(A1, k1, m1, v[0], v[1], v[2]);
    acc3(B0, k0, m0, v[3], v[4], v[5]);  acc3(B1, k1, m1, v[3], v[4], v[5]);
    acc3(C0, k0, m0, v[6], v[7], v[8]);  acc3(C1, k1, m1, v[6], v[7], v[8]);
    acc3(D0, k0, m0, v[9], v[10], v[11]); acc3(D1, k1, m1, v[9], v[10], v[11]);
    if (tail) {
        acc3(A2, k2, m2, v[0], v[1], v[2]);
        acc3(B2, k2, m2, v[3], v[4], v[5]);
        acc3(C2, k2, m2, v[6], v[7], v[8]);
        acc3(D2, k2, m2, v[9], v[10], v[11]);
    }

    #pragma unroll
    for (int o = 16; o > 0; o >>= 1) {
        #pragma unroll
        for (int i = 0; i < 12; i++)
            v[i] += __shfl_xor_sync(0xffffffffu, v[i], o);
    }

    if (lane == 0) {
        float cn0 = cninv[0], cn1 = cninv[1];
        #pragma unroll
        for (int i = 0; i < 4; i++) {
            int r = rbase + i;
            if (r < V) {
                float inv = 1.0f / fmaxf(sqrtf(v[3*i]), 1e-12f);
                vg_scr[r] = make_float2(v[3*i+1] * inv * cn0, v[3*i+2] * inv * cn1);
            }
        }
    }
}

// ---------------------------------------------------------------------------
// Kernel 2: gather vg + conv1d(2->2,K=111,pad55) + relu + channel-max + exp.
// grid (B, 2): each block handles 1024 positions (+55 halo each side).
// Writes UNNORMALIZED e=exp(s) + per-half sum to scratch.
// ---------------------------------------------------------------------------
__global__ void conv_exp_kernel(const int* __restrict__ inputs,
                                const float* __restrict__ conv_w,
                                const float* __restrict__ conv_b,
                                float* __restrict__ out, int beta_off) {
    __shared__ float sg0[SG2], sg1[SG2], sw[448], sred[256];
    int b = blockIdx.x, half = blockIdx.y, tid = threadIdx.x;
    int l0 = half * HL;

    for (int i = tid; i < SG2; i += 256) { sg0[i] = 0.f; sg1[i] = 0.f; }
    for (int t = tid; t < 448; t += 256) {                 // weights padded K=112
        int k = t % 112, ci = (t/112) & 1, o = t/224;
        sw[t] = (k < KW) ? conv_w[o*2*KW + ci*KW + k] : 0.f;
    }
    __syncthreads();
    for (int i = tid; i < HL + 111; i += 256) {
        int gl = l0 - 55 + i;
        if (gl >= 0 && gl < L) {
            float2 g = __ldg(&vg_scr[inputs[b*L + gl]]);
            sg0[i] = g.x; sg1[i] = g.y;
        }
    }
    __syncthreads();

    float cb0 = __ldg(conv_b + 0), cb1 = __ldg(conv_b + 1);
    int lp0 = tid * 4;
    float a0[4], a1[4], x0[4], x1[4];
    #pragma unroll
    for (int p = 0; p < 4; p++) {
        a0[p] = cb0; a1[p] = cb1;
        x0[p] = sg0[lp0+p]; x1[p] = sg1[lp0+p];
    }
    #pragma unroll 8
    for (int k = 0; k < 112; k++) {
        float w00 = sw[k], w01 = sw[112+k], w10 = sw[224+k], w11 = sw[336+k];
        #pragma unroll
        for (int p = 0; p < 4; p++) {
            float v0 = x0[(k+p)&3], v1 = x1[(k+p)&3];
            a0[p] += w00*v0 + w01*v1;
            a1[p] += w10*v0 + w11*v1;
        }
        x0[k&3] = sg0[lp0+k+4];
        x1[k&3] = sg1[lp0+k+4];
    }

    float e[4]; float lsum = 0.f;
    #pragma unroll
    for (int p = 0; p < 4; p++) {
        float s = fmaxf(0.f, fmaxf(a0[p], a1[p]));   // max(relu(a0),relu(a1))
        e[p] = expf(s);
        lsum += e[p];
    }
    float* bout = out + beta_off + b*L + l0 + lp0;
    #pragma unroll
    for (int p = 0; p < 4; p++) bout[p] = e[p];

    sred[tid] = lsum; __syncthreads();
    for (int st = 128; st > 0; st >>= 1) {
        if (tid < st) sred[tid] += sred[tid+st];
        __syncthreads();
    }
    if (tid == 0) esum_scr[b*2 + half] = sred[0];
}

// ---------------------------------------------------------------------------
// Kernel 3: chunk z-partial = sum_{l in chunk} beta[b,l]*emb[inputs[b,l]],
// immediately projected onto lin_w: opart[b,chunk] = (z_chunk·w0, z_chunk·w1).
// 608 thr = 8 groups x 75 float4 lanes; group accumulates 32 tokens (MLP 8).
// Normalizes beta on the fly and writes normalized beta back in-place.
// ---------------------------------------------------------------------------
__global__ void zacc_kernel(const int* __restrict__ inputs,
                            const float* __restrict__ emb,
                            const float* __restrict__ lin_w,
                            float* __restrict__ out, int beta_off) {
    __shared__ int   soff[CTOK];
    __shared__ float sb[CTOK];
    __shared__ __align__(16) float4 sacc[8][75];
    __shared__ float sr0[128], sr1[128];
    int b = blockIdx.x, chunk = blockIdx.y, tid = threadIdx.x;
    int l0 = chunk * CTOK;
    float invsum = 1.0f / (esum_scr[b*2] + esum_scr[b*2+1]);
    if (tid < CTOK) {
        soff[tid] = inputs[b*L + l0 + tid] * (int)(D * sizeof(float));
        float w = out[beta_off + b*L + l0 + tid] * invsum;
        sb[tid] = w;
        out[beta_off + b*L + l0 + tid] = w;     // normalized beta, final
    }
    if (tid >= CTOK && tid < CTOK + 128) {      // zero reduce buffers in parallel
        sr0[tid - CTOK] = 0.f; sr1[tid - CTOK] = 0.f;
    }
    __syncthreads();

    int g = tid / 75;              // group 0..7 (tid<600), rest idle
    int q = tid - g * 75;          // float4 lane 0..74
    if (g < 8) {
        float4 acc = make_float4(0.f, 0.f, 0.f, 0.f);
        int t0 = g * 32;
        #pragma unroll 8
        for (int i = 0; i < 32; i++) {
            int t = t0 + i;
            const float4* row = (const float4*)((const char*)emb + soff[t]);
            float w = sb[t];
            float4 v = __ldg(row + q);
            acc.x += w*v.x; acc.y += w*v.y; acc.z += w*v.z; acc.w += w*v.w;
        }
        sacc[g][q] = acc;
    }
    __syncthreads();

    if (tid < 75) {
        float4 s = make_float4(0.f, 0.f, 0.f, 0.f);
        #pragma unroll
        for (int gg = 0; gg < 8; gg++) {
            float4 a = sacc[gg][tid];
            s.x += a.x; s.y += a.y; s.z += a.z; s.w += a.w;
        }
        float4 w0 = __ldg((const float4*)lin_w + tid);
        float4 w1 = __ldg((const float4*)(lin_w + D) + tid);
        sr0[tid] = s.x*w0.x + s.y*w0.y + s.z*w0.z + s.w*w0.w;
        sr1[tid] = s.x*w1.x + s.y*w1.y + s.z*w1.z + s.w*w1.w;
    }
    __syncthreads();
    for (int st = 64; st > 0; st >>= 1) {
        if (tid < st) { sr0[tid] += sr0[tid+st]; sr1[tid] += sr1[tid+st]; }
        __syncthreads();
    }
    if (tid == 0)
        opart_scr[b*NCHUNK + chunk] = make_float2(sr0[0], sr1[0]);
}

// ---------------------------------------------------------------------------
// Kernel 4 (tiny): one block; thread b sums its 8 chunk partials + bias and
// emits log_softmax. 4KB total read.
// ---------------------------------------------------------------------------
__global__ void logits_final_kernel(const float* __restrict__ lin_b,
                                    float* __restrict__ out) {
    int b = threadIdx.x;
    if (b < B) {
        float o0 = __ldg(lin_b + 0), o1 = __ldg(lin_b + 1);
        #pragma unroll
        for (int c = 0; c < NCHUNK; c++) {
            float2 p = opart_scr[b*NCHUNK + c];
            o0 += p.x; o1 += p.y;
        }
        float m = fmaxf(o0, o1);
        float lse = m + logf(expf(o0 - m) + expf(o1 - m));
        out[b*2 + 0] = o0 - lse;
        out[b*2 + 1] = o1 - lse;
    }
}

// ---------------------------------------------------------------------------
extern "C" void kernel_launch(void* const* d_in, const int* in_sizes, int n_in,
                              void* d_out, int out_size) {
    const int*   inputs  = (const int*)  d_in[0];
    const float* emb     = (const float*)d_in[1];
    const float* cls     = (const float*)d_in[2];
    const float* conv_w  = (const float*)d_in[3];
    const float* conv_b  = (const float*)d_in[4];
    const float* lin_w   = (const float*)d_in[5];
    const float* lin_b   = (const float*)d_in[6];
    float* out = (float*)d_out;

    int beta_off = out_size - B*L;   // logits first, then beta [B,L]

    vocab_dot_kernel<<<(V + 31) / 32, 256>>>(emb, cls);                // 1563 blocks
    conv_exp_kernel<<<dim3(B, 2), 256>>>(inputs, conv_w, conv_b, out, beta_off);
    zacc_kernel<<<dim3(B, NCHUNK), 608>>>(inputs, emb, lin_w, out, beta_off);
    logits_final_kernel<<<1, B>>>(lin_b, out);
}

// round 13
// speedup vs baseline: 1.0409x; 1.0409x over previous
#include <cuda_runtime.h>
#include <math.h>

#define B 64
#define L 2048
#define D 300
#define KW 111
#define V 50000
#define NCHUNK 8         // token chunks per batch row in zacc
#define CTOK 256         // tokens per chunk
#define QL 512           // conv quarter-length per block
#define SG4 624          // 512 + 55 left halo + 57 right (incl. padded tap)

// ---- device scratch (no allocs allowed) ----
__device__ float2 vg_scr[V];                 // per-vocab normalized class dots
__device__ float2 opart_scr[B*NCHUNK];       // per-chunk (o0,o1) partials
__device__ float  esum_scr[B*4];             // per-quarter exp-sum partials

__device__ __forceinline__ void acc3(float4 e, float4 ka, float4 kb,
                                     float& ss, float& d0, float& d1) {
    ss += e.x*e.x + e.y*e.y + e.z*e.z + e.w*e.w;
    d0 += e.x*ka.x + e.y*ka.y + e.z*ka.z + e.w*ka.w;
    d1 += e.x*kb.x + e.y*kb.y + e.z*kb.z + e.w*kb.w;
}

// ---------------------------------------------------------------------------
// Kernel 1: per-VOCAB-row normalized class dots (60MB streaming read).
// FOUR rows per warp, all 12 float4 loads issued before any math.
// ---------------------------------------------------------------------------
__global__ void __launch_bounds__(256)
vocab_dot_kernel(const float* __restrict__ emb, const float* __restrict__ cls) {
    __shared__ __align__(16) float sc[2*D];
    __shared__ float cninv[2];
    int tid = threadIdx.x, warp = tid >> 5, lane = tid & 31;

    for (int i = tid; i < 2*D; i += 256) sc[i] = cls[i];
    __syncthreads();
    if (warp < 2) {
        float ss = 0.f;
        for (int d = lane; d < D; d += 32) { float v = sc[warp*D + d]; ss += v*v; }
        #pragma unroll
        for (int o = 16; o > 0; o >>= 1) ss += __shfl_xor_sync(0xffffffffu, ss, o);
        if (lane == 0) cninv[warp] = 1.0f / fmaxf(sqrtf(ss), 1e-12f);
    }
    __syncthreads();

    const float4* c0 = (const float4*)sc;
    const float4* c1 = (const float4*)(sc + D);
    bool tail = (lane < 11);
    float4 zf = make_float4(0.f,0.f,0.f,0.f);

    float4 k0 = c0[lane], k1 = c0[lane+32], k2 = tail ? c0[lane+64] : zf;
    float4 m0 = c1[lane], m1 = c1[lane+32], m2 = tail ? c1[lane+64] : zf;

    int rbase = blockIdx.x * 32 + warp * 4;          // 4 rows per warp
    int r0 = min(rbase,     V-1);
    int r1 = min(rbase + 1, V-1);
    int r2 = min(rbase + 2, V-1);
    int r3 = min(rbase + 3, V-1);
    const float4* p0 = (const float4*)(emb + (size_t)r0 * D);
    const float4* p1 = (const float4*)(emb + (size_t)r1 * D);
    const float4* p2 = (const float4*)(emb + (size_t)r2 * D);
    const float4* p3 = (const float4*)(emb + (size_t)r3 * D);

    float4 A0 = __ldg(p0 + lane), A1 = __ldg(p0 + lane + 32), A2 = tail ? __ldg(p0 + lane + 64) : zf;
    float4 B0 = __ldg(p1 + lane), B1 = __ldg(p1 + lane + 32), B2 = tail ? __ldg(p1 + lane + 64) : zf;
    float4 C0 = __ldg(p2 + lane), C1 = __ldg(p2 + lane + 32), C2 = tail ? __ldg(p2 + lane + 64) : zf;
    float4 D0 = __ldg(p3 + lane), D1 = __ldg(p3 + lane + 32), D2 = tail ? __ldg(p3 + lane + 64) : zf;

    float v[12];
    #pragma unroll
    for (int i = 0; i < 12; i++) v[i] = 0.f;
    acc3(A0, k0, m0, v[0], v[1], v[2]);  acc3(A1, k1, m1, v[0], v[1], v[2]);
    acc3(B0, k0, m0, v[3], v[4], v[5]);  acc3(B1, k1, m1, v[3], v[4], v[5]);
    acc3(C0, k0, m0, v[6], v[7], v[8]);  acc3(C1, k1, m1, v[6], v[7], v[8]);
    acc3(D0, k0, m0, v[9], v[10], v[11]); acc3(D1, k1, m1, v[9], v[10], v[11]);
    if (tail) {
        acc3(A2, k2, m2, v[0], v[1], v[2]);
        acc3(B2, k2, m2, v[3], v[4], v[5]);
        acc3(C2, k2, m2, v[6], v[7], v[8]);
        acc3(D2, k2, m2, v[9], v[10], v[11]);
    }

    #pragma unroll
    for (int o = 16; o > 0; o >>= 1) {
        #pragma unroll
        for (int i = 0; i < 12; i++)
            v[i] += __shfl_xor_sync(0xffffffffu, v[i], o);
    }

    if (lane == 0) {
        float cn0 = cninv[0], cn1 = cninv[1];
        #pragma unroll
        for (int i = 0; i < 4; i++) {
            int r = rbase + i;
            if (r < V) {
                float inv = 1.0f / fmaxf(sqrtf(v[3*i]), 1e-12f);
                vg_scr[r] = make_float2(v[3*i+1] * inv * cn0, v[3*i+2] * inv * cn1);
            }
        }
    }
}

// ---------------------------------------------------------------------------
// Kernel 2: conv1d + relu + channel-max + exp, quarter rows.
// grid (B,4), 128 thr, 4 pos/thread. Gather-or-zero sg fill (no zero pass).
// Writes UNNORMALIZED e=exp(s) + per-quarter sum to scratch.
// ---------------------------------------------------------------------------
__global__ void __launch_bounds__(128)
conv_exp_kernel(const int* __restrict__ inputs,
                const float* __restrict__ conv_w,
                const float* __restrict__ conv_b,
                float* __restrict__ out, int beta_off) {
    __shared__ float sg0[SG4], sg1[SG4], sw[448], sred[128];
    int b = blockIdx.x, quart = blockIdx.y, tid = threadIdx.x;
    int l0 = quart * QL;

    for (int t = tid; t < 448; t += 128) {                 // weights padded K=112
        int k = t % 112, ci = (t/112) & 1, o = t/224;
        sw[t] = (k < KW) ? conv_w[o*2*KW + ci*KW + k] : 0.f;
    }
    #pragma unroll
    for (int j = 0; j < 5; j++) {
        int i = tid + j*128;
        int gl = l0 - 55 + i;
        if (i < SG4) {
            bool valid = (gl >= 0) && (gl < L);
            float2 g = valid ? __ldg(&vg_scr[inputs[b*L + (valid ? gl : 0)]])
                             : make_float2(0.f, 0.f);
            sg0[i] = g.x; sg1[i] = g.y;
        }
    }
    float cb0 = __ldg(conv_b + 0), cb1 = __ldg(conv_b + 1);
    __syncthreads();

    int lp0 = tid * 4;
    float a0[4], a1[4], x0[4], x1[4];
    #pragma unroll
    for (int p = 0; p < 4; p++) {
        a0[p] = cb0; a1[p] = cb1;
        x0[p] = sg0[lp0+p]; x1[p] = sg1[lp0+p];
    }
    #pragma unroll 8
    for (int k = 0; k < 112; k++) {
        float w00 = sw[k], w01 = sw[112+k], w10 = sw[224+k], w11 = sw[336+k];
        #pragma unroll
        for (int p = 0; p < 4; p++) {
            float v0 = x0[(k+p)&3], v1 = x1[(k+p)&3];
            a0[p] += w00*v0 + w01*v1;
            a1[p] += w10*v0 + w11*v1;
        }
        x0[k&3] = sg0[lp0+k+4];
        x1[k&3] = sg1[lp0+k+4];
    }

    float e[4]; float lsum = 0.f;
    #pragma unroll
    for (int p = 0; p < 4; p++) {
        float s = fmaxf(0.f, fmaxf(a0[p], a1[p]));   // max(relu(a0),relu(a1))
        e[p] = expf(s);
        lsum += e[p];
    }
    float* bout = out + beta_off + b*L + l0 + lp0;
    #pragma unroll
    for (int p = 0; p < 4; p++) bout[p] = e[p];

    sred[tid] = lsum; __syncthreads();
    for (int st = 64; st > 0; st >>= 1) {
        if (tid < st) sred[tid] += sred[tid+st];
        __syncthreads();
    }
    if (tid == 0) esum_scr[b*4 + quart] = sred[0];
}

// ---------------------------------------------------------------------------
// Kernel 3: chunk z-partial = sum_{l in chunk} beta[b,l]*emb[inputs[b,l]],
// immediately projected onto lin_w: opart[b,chunk] = (z_chunk·w0, z_chunk·w1).
// 608 thr = 8 groups x 75 float4 lanes; normalizes beta in-place.
// ---------------------------------------------------------------------------
__global__ void zacc_kernel(const int* __restrict__ inputs,
                            const float* __restrict__ emb,
                            const float* __restrict__ lin_w,
                            float* __restrict__ out, int beta_off) {
    __shared__ int   soff[CTOK];
    __shared__ float sb[CTOK];
    __shared__ __align__(16) float4 sacc[8][75];
    __shared__ float sr0[128], sr1[128];
    int b = blockIdx.x, chunk = blockIdx.y, tid = threadIdx.x;
    int l0 = chunk * CTOK;

    float invsum = 1.0f / (esum_scr[b*4] + esum_scr[b*4+1] +
                           esum_scr[b*4+2] + esum_scr[b*4+3]);
    if (tid < CTOK) {
        soff[tid] = inputs[b*L + l0 + tid] * (int)(D * sizeof(float));
        float w = out[beta_off + b*L + l0 + tid] * invsum;
        sb[tid] = w;
        out[beta_off + b*L + l0 + tid] = w;     // normalized beta, final
    }
    if (tid >= CTOK && tid < CTOK + 128) {
        sr0[tid - CTOK] = 0.f; sr1[tid - CTOK] = 0.f;
    }
    __syncthreads();

    int g = tid / 75;              // group 0..7 (tid<600), rest idle
    int q = tid - g * 75;          // float4 lane 0..74
    if (g < 8) {
        float4 acc = make_float4(0.f, 0.f, 0.f, 0.f);
        int t0 = g * 32;
        #pragma unroll 8
        for (int i = 0; i < 32; i++) {
            int t = t0 + i;
            const float4* row = (const float4*)((const char*)emb + soff[t]);
            float w = sb[t];
            float4 v = __ldg(row + q);
            acc.x += w*v.x; acc.y += w*v.y; acc.z += w*v.z; acc.w += w*v.w;
        }
        sacc[g][q] = acc;
    }
    __syncthreads();

    if (tid < 75) {
        float4 s = make_float4(0.f, 0.f, 0.f, 0.f);
        #pragma unroll
        for (int gg = 0; gg < 8; gg++) {
            float4 a = sacc[gg][tid];
            s.x += a.x; s.y += a.y; s.z += a.z; s.w += a.w;
        }
        float4 w0 = __ldg((const float4*)lin_w + tid);
        float4 w1 = __ldg((const float4*)(lin_w + D) + tid);
        sr0[tid] = s.x*w0.x + s.y*w0.y + s.z*w0.z + s.w*w0.w;
        sr1[tid] = s.x*w1.x + s.y*w1.y + s.z*w1.z + s.w*w1.w;
    }
    __syncthreads();
    for (int st = 64; st > 0; st >>= 1) {
        if (tid < st) { sr0[tid] += sr0[tid+st]; sr1[tid] += sr1[tid+st]; }
        __syncthreads();
    }
    if (tid == 0)
        opart_scr[b*NCHUNK + chunk] = make_float2(sr0[0], sr1[0]);
}

// ---------------------------------------------------------------------------
// Kernel 4 (tiny): thread b sums its 8 chunk partials + bias, log_softmax.
// ---------------------------------------------------------------------------
__global__ void logits_final_kernel(const float* __restrict__ lin_b,
                                    float* __restrict__ out) {
    int b = threadIdx.x;
    if (b < B) {
        float o0 = __ldg(lin_b + 0), o1 = __ldg(lin_b + 1);
        #pragma unroll
        for (int c = 0; c < NCHUNK; c++) {
            float2 p = opart_scr[b*NCHUNK + c];
            o0 += p.x; o1 += p.y;
        }
        float m = fmaxf(o0, o1);
        float lse = m + logf(expf(o0 - m) + expf(o1 - m));
        out[b*2 + 0] = o0 - lse;
        out[b*2 + 1] = o1 - lse;
    }
}

// ---------------------------------------------------------------------------
extern "C" void kernel_launch(void* const* d_in, const int* in_sizes, int n_in,
                              void* d_out, int out_size) {
    const int*   inputs  = (const int*)  d_in[0];
    const float* emb     = (const float*)d_in[1];
    const float* cls     = (const float*)d_in[2];
    const float* conv_w  = (const float*)d_in[3];
    const float* conv_b  = (const float*)d_in[4];
    const float* lin_w   = (const float*)d_in[5];
    const float* lin_b   = (const float*)d_in[6];
    float* out = (float*)d_out;

    int beta_off = out_size - B*L;   // logits first, then beta [B,L]

    vocab_dot_kernel<<<(V + 31) / 32, 256>>>(emb, cls);                // 1563 blocks
    conv_exp_kernel<<<dim3(B, 4), 128>>>(inputs, conv_w, conv_b, out, beta_off);
    zacc_kernel<<<dim3(B, NCHUNK), 608>>>(inputs, emb, lin_w, out, beta_off);
    logits_final_kernel<<<1, B>>>(lin_b, out);
}

// round 16
// speedup vs baseline: 1.1921x; 1.1452x over previous
#include <cuda_runtime.h>
#include <math.h>

#define B 64
#define L 2048
#define D 300
#define KW 111
#define V 50000
#define QL 512           // conv quarter-length per block
#define SG4 624          // 512 + 55 left halo + 57 right (incl. padded tap)

// ---- device scratch (no allocs allowed) ----
__device__ float2 vg_scr[V];     // per-vocab normalized class dots
__device__ float2 pw_scr[V];     // per-vocab raw lin_w dots (emb.w0, emb.w1)
__device__ float  esum_scr[B*4]; // per-quarter exp-sum partials

__device__ __forceinline__ void acc5(float4 e, float4 ka, float4 kb,
                                     float4 wa, float4 wb,
                                     float& ss, float& d0, float& d1,
                                     float& p0, float& p1) {
    ss += e.x*e.x + e.y*e.y + e.z*e.z + e.w*e.w;
    d0 += e.x*ka.x + e.y*ka.y + e.z*ka.z + e.w*ka.w;
    d1 += e.x*kb.x + e.y*kb.y + e.z*kb.z + e.w*kb.w;
    p0 += e.x*wa.x + e.y*wa.y + e.z*wa.z + e.w*wa.w;
    p1 += e.x*wb.x + e.y*wb.y + e.z*wb.z + e.w*wb.w;
}

// ---------------------------------------------------------------------------
// Kernel 1: per-VOCAB-row dots (60MB streaming read): normalized class dots
// (vg) AND raw lin_w dots (pw). TWO rows per warp (10-value butterfly,
// moderate register pressure), 6 row-loads issued up front.
// ---------------------------------------------------------------------------
__global__ void __launch_bounds__(256)
vocab_dot_kernel(const float* __restrict__ emb, const float* __restrict__ cls,
                 const float* __restrict__ lin_w) {
    __shared__ __align__(16) float sc[2*D];
    __shared__ __align__(16) float sl[2*D];
    __shared__ float cninv[2];
    int tid = threadIdx.x, warp = tid >> 5, lane = tid & 31;

    for (int i = tid; i < 2*D; i += 256) { sc[i] = cls[i]; sl[i] = lin_w[i]; }
    __syncthreads();
    if (warp < 2) {
        float ss = 0.f;
        for (int d = lane; d < D; d += 32) { float v = sc[warp*D + d]; ss += v*v; }
        #pragma unroll
        for (int o = 16; o > 0; o >>= 1) ss += __shfl_xor_sync(0xffffffffu, ss, o);
        if (lane == 0) cninv[warp] = 1.0f / fmaxf(sqrtf(ss), 1e-12f);
    }
    __syncthreads();

    const float4* c0 = (const float4*)sc;
    const float4* c1 = (const float4*)(sc + D);
    const float4* l0v = (const float4*)sl;
    const float4* l1v = (const float4*)(sl + D);
    bool tail = (lane < 11);
    float4 zf = make_float4(0.f,0.f,0.f,0.f);

    int r = blockIdx.x * 16 + warp * 2;              // 2 rows per warp; grid*16==V
    const float4* pA = (const float4*)(emb + (size_t)r * D);
    const float4* pB = (const float4*)(emb + (size_t)(r+1) * D);

    // issue all 6 loads before any math
    float4 A0 = __ldg(pA + lane);
    float4 A1 = __ldg(pA + lane + 32);
    float4 A2 = tail ? __ldg(pA + lane + 64) : zf;
    float4 B0 = __ldg(pB + lane);
    float4 B1 = __ldg(pB + lane + 32);
    float4 B2 = tail ? __ldg(pB + lane + 64) : zf;

    float v[10];
    #pragma unroll
    for (int i = 0; i < 10; i++) v[i] = 0.f;

    {   // q = lane
        float4 ka = c0[lane], kb = c1[lane], wa = l0v[lane], wb = l1v[lane];
        acc5(A0, ka, kb, wa, wb, v[0], v[1], v[2], v[3], v[4]);
        acc5(B0, ka, kb, wa, wb, v[5], v[6], v[7], v[8], v[9]);
    }
    {   // q = lane+32
        float4 ka = c0[lane+32], kb = c1[lane+32], wa = l0v[lane+32], wb = l1v[lane+32];
        acc5(A1, ka, kb, wa, wb, v[0], v[1], v[2], v[3], v[4]);
        acc5(B1, ka, kb, wa, wb, v[5], v[6], v[7], v[8], v[9]);
    }
    if (tail) { // q = lane+64
        float4 ka = c0[lane+64], kb = c1[lane+64], wa = l0v[lane+64], wb = l1v[lane+64];
        acc5(A2, ka, kb, wa, wb, v[0], v[1], v[2], v[3], v[4]);
        acc5(B2, ka, kb, wa, wb, v[5], v[6], v[7], v[8], v[9]);
    }

    #pragma unroll
    for (int o = 16; o > 0; o >>= 1) {
        #pragma unroll
        for (int i = 0; i < 10; i++)
            v[i] += __shfl_xor_sync(0xffffffffu, v[i], o);
    }

    if (lane == 0) {
        float cn0 = cninv[0], cn1 = cninv[1];
        float invA = 1.0f / fmaxf(sqrtf(v[0]), 1e-12f);
        float invB = 1.0f / fmaxf(sqrtf(v[5]), 1e-12f);
        vg_scr[r]   = make_float2(v[1] * invA * cn0, v[2] * invA * cn1);
        pw_scr[r]   = make_float2(v[3], v[4]);
        vg_scr[r+1] = make_float2(v[6] * invB * cn0, v[7] * invB * cn1);
        pw_scr[r+1] = make_float2(v[8], v[9]);
    }
}

// ---------------------------------------------------------------------------
// Kernel 2: conv1d + relu + channel-max + exp, quarter rows.
// grid (B,4), 128 thr, 4 pos/thread. Gather-or-zero sg fill.
// Writes UNNORMALIZED e=exp(s) + per-quarter sum to scratch.
// ---------------------------------------------------------------------------
__global__ void __launch_bounds__(128)
conv_exp_kernel(const int* __restrict__ inputs,
                const float* __restrict__ conv_w,
                const float* __restrict__ conv_b,
                float* __restrict__ out, int beta_off) {
    __shared__ float sg0[SG4], sg1[SG4], sw[448], sred[128];
    int b = blockIdx.x, quart = blockIdx.y, tid = threadIdx.x;
    int l0 = quart * QL;

    for (int t = tid; t < 448; t += 128) {                 // weights padded K=112
        int k = t % 112, ci = (t/112) & 1, o = t/224;
        sw[t] = (k < KW) ? conv_w[o*2*KW + ci*KW + k] : 0.f;
    }
    #pragma unroll
    for (int j = 0; j < 5; j++) {
        int i = tid + j*128;
        int gl = l0 - 55 + i;
        if (i < SG4) {
            bool valid = (gl >= 0) && (gl < L);
            float2 g = valid ? __ldg(&vg_scr[inputs[b*L + (valid ? gl : 0)]])
                             : make_float2(0.f, 0.f);
            sg0[i] = g.x; sg1[i] = g.y;
        }
    }
    float cb0 = __ldg(conv_b + 0), cb1 = __ldg(conv_b + 1);
    __syncthreads();

    int lp0 = tid * 4;
    float a0[4], a1[4], x0[4], x1[4];
    #pragma unroll
    for (int p = 0; p < 4; p++) {
        a0[p] = cb0; a1[p] = cb1;
        x0[p] = sg0[lp0+p]; x1[p] = sg1[lp0+p];
    }
    #pragma unroll 8
    for (int k = 0; k < 112; k++) {
        float w00 = sw[k], w01 = sw[112+k], w10 = sw[224+k], w11 = sw[336+k];
        #pragma unroll
        for (int p = 0; p < 4; p++) {
            float v0 = x0[(k+p)&3], v1 = x1[(k+p)&3];
            a0[p] += w00*v0 + w01*v1;
            a1[p] += w10*v0 + w11*v1;
        }
        x0[k&3] = sg0[lp0+k+4];
        x1[k&3] = sg1[lp0+k+4];
    }

    float e[4]; float lsum = 0.f;
    #pragma unroll
    for (int p = 0; p < 4; p++) {
        float s = fmaxf(0.f, fmaxf(a0[p], a1[p]));   // max(relu(a0),relu(a1))
        e[p] = expf(s);
        lsum += e[p];
    }
    float* bout = out + beta_off + b*L + l0 + lp0;
    #pragma unroll
    for (int p = 0; p < 4; p++) bout[p] = e[p];

    sred[tid] = lsum; __syncthreads();
    for (int st = 64; st > 0; st >>= 1) {
        if (tid < st) sred[tid] += sred[tid+st];
        __syncthreads();
    }
    if (tid == 0) esum_scr[b*4 + quart] = sred[0];
}

// ---------------------------------------------------------------------------
// Kernel 3: per batch row — normalize beta in place AND accumulate
// logits[b] = sum_l beta[b,l] * pw[inputs[b,l]] + lin_b, then log_softmax.
// One block (256 thr) per row; ~3MB total traffic across the grid.
// ---------------------------------------------------------------------------
__global__ void __launch_bounds__(256)
beta_logits_kernel(const int* __restrict__ inputs,
                   const float* __restrict__ lin_b,
                   float* __restrict__ out, int beta_off) {
    __shared__ float sr0[256], sr1[256];
    int b = blockIdx.x, tid = threadIdx.x;
    float invsum = 1.0f / (esum_scr[b*4] + esum_scr[b*4+1] +
                           esum_scr[b*4+2] + esum_scr[b*4+3]);
    float o0 = 0.f, o1 = 0.f;
    #pragma unroll
    for (int j = 0; j < 8; j++) {                  // L/256 = 8
        int l = tid + j*256;
        float w = out[beta_off + b*L + l] * invsum;
        out[beta_off + b*L + l] = w;               // normalized beta, final
        float2 p = __ldg(&pw_scr[inputs[b*L + l]]);
        o0 += w * p.x;
        o1 += w * p.y;
    }
    sr0[tid] = o0; sr1[tid] = o1; __syncthreads();
    for (int st = 128; st > 0; st >>= 1) {
        if (tid < st) { sr0[tid] += sr0[tid+st]; sr1[tid] += sr1[tid+st]; }
        __syncthreads();
    }
    if (tid == 0) {
        float a = sr0[0] + __ldg(lin_b + 0);
        float c = sr1[0] + __ldg(lin_b + 1);
        float m = fmaxf(a, c);
        float lse = m + logf(expf(a - m) + expf(c - m));
        out[b*2 + 0] = a - lse;
        out[b*2 + 1] = c - lse;
    }
}

// ---------------------------------------------------------------------------
extern "C" void kernel_launch(void* const* d_in, const int* in_sizes, int n_in,
                              void* d_out, int out_size) {
    const int*   inputs  = (const int*)  d_in[0];
    const float* emb     = (const float*)d_in[1];
    const float* cls     = (const float*)d_in[2];
    const float* conv_w  = (const float*)d_in[3];
    const float* conv_b  = (const float*)d_in[4];
    const float* lin_w   = (const float*)d_in[5];
    const float* lin_b   = (const float*)d_in[6];
    float* out = (float*)d_out;

    int beta_off = out_size - B*L;   // logits first, then beta [B,L]

    vocab_dot_kernel<<<V/16, 256>>>(emb, cls, lin_w);            // 3125 blocks
    conv_exp_kernel<<<dim3(B, 4), 128>>>(inputs, conv_w, conv_b, out, beta_off);
    beta_logits_kernel<<<B, 256>>>(inputs, lin_b, out, beta_off);
}